// round 16
// baseline (speedup 1.0000x reference)
#include <cuda_runtime.h>
#include <cstdint>

#define NN 50000
#define EE 800000
#define D  128
#define DE 16
#define NSB 49           // scan blocks: ceil(50000/1024)
#define AGG_BLOCKS 296   // 148 SMs x 2 resident blocks -> 2368 persistent warps

#define NODE_SMEM (2*D*D*4 + 4*D*4)

// Scratch (static __device__ arrays: no allocation allowed)
__device__ float g_h[2][NN * D];
__device__ float g_S[NN * D];
__device__ float g_Z[NN * D];
__device__ int   g_deg[NN];
__device__ float g_gn[NN];
__device__ int   g_off[NN + 1];
__device__ int   g_cur[NN];
__device__ int   g_pre[NN];                 // block-local exclusive prefix
__device__ int   g_bsum[64];                // per-block sums -> exclusive prefix
__device__ int2  g_prw[EE];                 // {row, bitcast(w)} dest-sorted
__device__ float g_eas[(size_t)EE * DE];    // edge_attr in dest-sorted order

#define PACK2(d, x)      asm("mov.b64 %0, {%1, %1};" : "=l"(d) : "f"(x))
#define FMA2(d, a, b, c) asm("fma.rn.f32x2 %0, %1, %2, %3;" : "=l"(d) : "l"(a), "l"(b), "l"(c))
#define PREF_L1(p)       asm volatile("prefetch.global.L1 [%0];" :: "l"(p))

__global__ void k_zero_deg() {
    int i = blockIdx.x * blockDim.x + threadIdx.x;
    if (i < NN) g_deg[i] = 0;
}

__global__ void k_deg(const int* __restrict__ col) {
    int e = blockIdx.x * blockDim.x + threadIdx.x;
    if (e < EE) atomicAdd(&g_deg[col[e]], 1);
}

// Pass 1: block-local exclusive scan of g_deg; write local prefix + block sum.
__global__ __launch_bounds__(1024) void k_scan1() {
    __shared__ int sw[32];
    const int t = threadIdx.x, lane = t & 31, wid = t >> 5;
    const int i = blockIdx.x * 1024 + t;
    const int v = (i < NN) ? g_deg[i] : 0;
    int x = v;
#pragma unroll
    for (int o = 1; o < 32; o <<= 1) {
        int y = __shfl_up_sync(0xffffffffu, x, o);
        if (lane >= o) x += y;
    }
    if (lane == 31) sw[wid] = x;
    __syncthreads();
    if (wid == 0) {
        int s = sw[lane];
#pragma unroll
        for (int o = 1; o < 32; o <<= 1) {
            int y = __shfl_up_sync(0xffffffffu, s, o);
            if (lane >= o) s += y;
        }
        sw[lane] = s;
    }
    __syncthreads();
    const int pre = (wid ? sw[wid - 1] : 0) + x - v;  // exclusive within block
    if (i < NN) g_pre[i] = pre;
    if (t == 1023) g_bsum[blockIdx.x] = pre + v;
}

// Pass 2: one warp scans the 49 block sums (exclusive).
__global__ void k_scan2() {
    const int lane = threadIdx.x;
    if (lane >= 32) return;
    int a = 0, b = 0;
    if (lane < NSB) a = g_bsum[lane];
    if (lane + 32 < NSB) b = g_bsum[lane + 32];
    const int a0 = a, b0 = b;
#pragma unroll
    for (int o = 1; o < 32; o <<= 1) {
        int y = __shfl_up_sync(0xffffffffu, a, o);
        if (lane >= o) a += y;
    }
    const int totA = __shfl_sync(0xffffffffu, a, 31);
#pragma unroll
    for (int o = 1; o < 32; o <<= 1) {
        int y = __shfl_up_sync(0xffffffffu, b, o);
        if (lane >= o) b += y;
    }
    if (lane < NSB) g_bsum[lane] = a - a0;
    if (lane + 32 < NSB) g_bsum[lane + 32] = totA + b - b0;
}

// Pass 3: finalize offsets, cursors, gcn-norm factors.
__global__ __launch_bounds__(1024) void k_fin() {
    const int i = blockIdx.x * 1024 + threadIdx.x;
    if (i < NN) {
        const int o = g_pre[i] + g_bsum[blockIdx.x];
        g_off[i] = o;
        g_cur[i] = o;
        const int d = g_deg[i];
        g_gn[i] = (d > 0) ? rsqrtf((float)d) : 0.f;
    }
    if (i == 0) g_off[NN] = EE;
}

// Counting-sort permute: edge e -> slot pos (sorted by destination col).
__global__ void k_perm(const int* __restrict__ row, const int* __restrict__ col,
                       const float* __restrict__ eattr) {
    int e = blockIdx.x * blockDim.x + threadIdx.x;
    if (e >= EE) return;
    const int c = col[e];
    const int r = row[e];
    const int pos = atomicAdd(&g_cur[c], 1);
    g_prw[pos] = make_int2(r, __float_as_int(g_gn[r] * g_gn[c]));
    const float4* src = (const float4*)(eattr + (size_t)e * DE);
    float4* dst = (float4*)(g_eas + (size_t)pos * DE);
    dst[0] = src[0]; dst[1] = src[1]; dst[2] = src[2]; dst[3] = src[3];
}

// Persistent warps: W1/b1 loaded ONCE per warp, grid-stride node loop with
// round-7's 2-edge body. NEW: at each node's start, lanes cooperatively
// prefetch the NEXT node's eas/prw lines into L1 (covers DRAM first-touch).
__global__ __launch_bounds__(256, 2) void k_agg(
    const float* __restrict__ x,
    const float* __restrict__ w1,
    const float* __restrict__ b1,
    int layer)
{
    const float* __restrict__ h = (layer == 0) ? x : g_h[(layer - 1) & 1];
    const int lane = threadIdx.x & 31;

    // W1 columns for this lane in registers as f32x2 pairs (amortized over ~21 nodes)
    unsigned long long w101[DE], w123[DE], b101, b123;
    {
        const ulonglong2 bv = *(const ulonglong2*)(b1 + lane * 4);
        b101 = bv.x; b123 = bv.y;
#pragma unroll
        for (int k = 0; k < DE; ++k) {
            const ulonglong2 wv = *(const ulonglong2*)(w1 + k * D + lane * 4);
            w101[k] = wv.x; w123[k] = wv.y;
        }
    }

    const int warp   = blockIdx.x * 8 + (threadIdx.x >> 5);
    const int nwarps = gridDim.x * 8;

    for (int node = warp; node < NN; node += nwarps) {
        // cooperative L1 prefetch of the NEXT node's metadata (one body of cover)
        const int nxt = node + nwarps;
        if (nxt < NN) {
            const int nj0 = __ldg(g_off + nxt);
            const int nj1 = __ldg(g_off + nxt + 1);
            const int nc = nj1 - nj0;
            // eas: 128B line = 2 edges; lane l covers edges [2l, 2l+1]
            if (lane * 2 < nc) PREF_L1(g_eas + (size_t)(nj0 + lane * 2) * DE);
            // prw: 128B line = 16 edges; lanes 29..31 cover up to 48 edges
            if (lane == 29) PREF_L1(g_prw + nj0);
            if (lane == 30 && nc > 16) PREF_L1(g_prw + nj0 + 16);
            if (lane == 31 && nc > 32) PREF_L1(g_prw + nj0 + 32);
        }

        const int j0 = g_off[node], j1 = g_off[node + 1];
        const int cnt = j1 - j0;

        unsigned long long s01 = 0ull, s23 = 0ull;
        float az0 = 0.f, az1 = 0.f, az2 = 0.f, az3 = 0.f;

        const int npairs = cnt >> 1;
        const bool tail = (cnt & 1) != 0;

        int2 rwA = make_int2(0, 0), rwB = make_int2(0, 0);
        float aA = 0.f, aB = 0.f;
        if (cnt > 0) {
            rwA = __ldg(g_prw + j0);
            aA = (lane < DE) ? __ldg(g_eas + (size_t)j0 * DE + lane) : 0.f;
        }
        if (npairs > 0) {
            rwB = __ldg(g_prw + j0 + 1);
            aB = (lane < DE) ? __ldg(g_eas + (size_t)(j0 + 1) * DE + lane) : 0.f;
        }

        int j = j0;
        for (int p = 0; p < npairs; ++p) {
            const ulonglong2 hvA = __ldg((const ulonglong2*)(h + (size_t)rwA.x * D + lane * 4));
            const ulonglong2 hvB = __ldg((const ulonglong2*)(h + (size_t)rwB.x * D + lane * 4));
            const float wA = __int_as_float(rwA.y);
            const float wB = __int_as_float(rwB.y);
            const float aAc = aA, aBc = aB;

            const int jn = j + 2;
            if (p + 1 < npairs) {
                rwA = __ldg(g_prw + jn);
                rwB = __ldg(g_prw + jn + 1);
                aA = (lane < DE) ? __ldg(g_eas + (size_t)jn * DE + lane) : 0.f;
                aB = (lane < DE) ? __ldg(g_eas + (size_t)(jn + 1) * DE + lane) : 0.f;
            } else if (tail) {
                rwA = __ldg(g_prw + jn);
                aA = (lane < DE) ? __ldg(g_eas + (size_t)jn * DE + lane) : 0.f;
            }

            // two independent edge-MLP chains
            unsigned long long zA01 = b101, zA23 = b123, zB01 = b101, zB23 = b123;
#pragma unroll
            for (int k = 0; k < DE; ++k) {
                const float akA = __shfl_sync(0xffffffffu, aAc, k);
                const float akB = __shfl_sync(0xffffffffu, aBc, k);
                unsigned long long tA, tB;
                PACK2(tA, akA);
                PACK2(tB, akB);
                FMA2(zA01, tA, w101[k], zA01);
                FMA2(zB01, tB, w101[k], zB01);
                FMA2(zA23, tA, w123[k], zA23);
                FMA2(zB23, tB, w123[k], zB23);
            }
            {
                const float2 p01 = *(const float2*)&zA01, p23 = *(const float2*)&zA23;
                const float2 q01 = *(const float2*)&zB01, q23 = *(const float2*)&zB23;
                az0 += fmaxf(p01.x, 0.f) + fmaxf(q01.x, 0.f);
                az1 += fmaxf(p01.y, 0.f) + fmaxf(q01.y, 0.f);
                az2 += fmaxf(p23.x, 0.f) + fmaxf(q23.x, 0.f);
                az3 += fmaxf(p23.y, 0.f) + fmaxf(q23.y, 0.f);
            }
            unsigned long long wp;
            PACK2(wp, wA);
            FMA2(s01, wp, hvA.x, s01);
            FMA2(s23, wp, hvA.y, s23);
            PACK2(wp, wB);
            FMA2(s01, wp, hvB.x, s01);
            FMA2(s23, wp, hvB.y, s23);
            j = jn;
        }

        if (tail) {
            // metadata already in rwA/aA (prefetched by last pair, or the cnt>0 init)
            const ulonglong2 hvA = __ldg((const ulonglong2*)(h + (size_t)rwA.x * D + lane * 4));
            const float wA = __int_as_float(rwA.y);
            unsigned long long zA01 = b101, zA23 = b123;
#pragma unroll
            for (int k = 0; k < DE; ++k) {
                const float ak = __shfl_sync(0xffffffffu, aA, k);
                unsigned long long tA; PACK2(tA, ak);
                FMA2(zA01, tA, w101[k], zA01);
                FMA2(zA23, tA, w123[k], zA23);
            }
            const float2 p01 = *(const float2*)&zA01, p23 = *(const float2*)&zA23;
            az0 += fmaxf(p01.x, 0.f);
            az1 += fmaxf(p01.y, 0.f);
            az2 += fmaxf(p23.x, 0.f);
            az3 += fmaxf(p23.y, 0.f);
            unsigned long long wp; PACK2(wp, wA);
            FMA2(s01, wp, hvA.x, s01);
            FMA2(s23, wp, hvA.y, s23);
        }

        ulonglong2 so; so.x = s01; so.y = s23;
        *(ulonglong2*)(g_S + (size_t)node * D + lane * 4) = so;
        *(float4*)(g_Z + (size_t)node * D + lane * 4) = make_float4(az0, az1, az2, az3);
    }
}

// Fused: out = S @ lin_w + Z @ W2 + deg*b2 + bias ; LayerNorm ; relu  (f32x2 GEMM)
__global__ __launch_bounds__(512, 1) void k_node(
    const float* __restrict__ lw,
    const float* __restrict__ w2,
    const float* __restrict__ b2,
    const float* __restrict__ bias,
    const float* __restrict__ lnw,
    const float* __restrict__ lnb,
    float* __restrict__ dout,
    int layer)
{
    extern __shared__ __align__(16) float sm[];
    float* s_lw  = sm;
    float* s_w2  = sm + D * D;
    float* s_vec = sm + 2 * D * D;   // [b2 | bias | lnw | lnb]

    for (int i = threadIdx.x; i < D * D / 4; i += 512) {
        ((float4*)s_lw)[i] = ((const float4*)lw)[i];
        ((float4*)s_w2)[i] = ((const float4*)w2)[i];
    }
    if (threadIdx.x < D) {
        s_vec[threadIdx.x]         = b2[threadIdx.x];
        s_vec[D     + threadIdx.x] = bias[threadIdx.x];
        s_vec[2 * D + threadIdx.x] = lnw[threadIdx.x];
        s_vec[3 * D + threadIdx.x] = lnb[threadIdx.x];
    }
    __syncthreads();

    float* hout = (layer == 2) ? dout : g_h[layer & 1];
    const int lane = threadIdx.x & 31;
    const int wid  = threadIdx.x >> 5;
    const ulonglong2* lw2 = (const ulonglong2*)s_lw;
    const ulonglong2* w22 = (const ulonglong2*)s_w2;

    for (int tile = blockIdx.x * 64; tile < NN; tile += gridDim.x * 64) {
        const int r0 = tile + wid * 4;
        unsigned long long acc01[4], acc23[4];
#pragma unroll
        for (int i = 0; i < 4; ++i) { acc01[i] = 0ull; acc23[i] = 0ull; }

#pragma unroll 2
        for (int k = 0; k < D; k += 4) {
            float4 sv[4], zv[4];
#pragma unroll
            for (int i = 0; i < 4; ++i) {
                const int r = r0 + i;
                if (r < NN) {
                    sv[i] = __ldg((const float4*)(g_S + (size_t)r * D + k));
                    zv[i] = __ldg((const float4*)(g_Z + (size_t)r * D + k));
                } else {
                    sv[i] = make_float4(0.f, 0.f, 0.f, 0.f);
                    zv[i] = make_float4(0.f, 0.f, 0.f, 0.f);
                }
            }
#pragma unroll
            for (int kk = 0; kk < 4; ++kk) {
                const ulonglong2 wl = lw2[(k + kk) * 32 + lane];
                const ulonglong2 wv = w22[(k + kk) * 32 + lane];
#pragma unroll
                for (int i = 0; i < 4; ++i) {
                    const float sx = ((const float*)&sv[i])[kk];
                    const float zx = ((const float*)&zv[i])[kk];
                    unsigned long long sx2, zx2;
                    PACK2(sx2, sx);
                    PACK2(zx2, zx);
                    FMA2(acc01[i], sx2, wl.x, acc01[i]);
                    FMA2(acc01[i], zx2, wv.x, acc01[i]);
                    FMA2(acc23[i], sx2, wl.y, acc23[i]);
                    FMA2(acc23[i], zx2, wv.y, acc23[i]);
                }
            }
        }

        // Epilogue: +deg*b2 +bias, LayerNorm, relu, store
#pragma unroll
        for (int i = 0; i < 4; ++i) {
            const int r = r0 + i;
            if (r >= NN) continue;
            const float dg = (float)g_deg[r];
            const float2 a01 = *(const float2*)&acc01[i];
            const float2 a23 = *(const float2*)&acc23[i];
            float o[4] = { a01.x, a01.y, a23.x, a23.y };
#pragma unroll
            for (int jj = 0; jj < 4; ++jj) {
                const int c = lane * 4 + jj;
                o[jj] = o[jj] + dg * s_vec[c] + s_vec[D + c];
            }
            float sum = o[0] + o[1] + o[2] + o[3];
#pragma unroll
            for (int off = 16; off > 0; off >>= 1)
                sum += __shfl_xor_sync(0xffffffffu, sum, off);
            const float mu = sum * (1.f / D);
            float sq = 0.f;
#pragma unroll
            for (int jj = 0; jj < 4; ++jj) { const float dd = o[jj] - mu; sq = fmaf(dd, dd, sq); }
#pragma unroll
            for (int off = 16; off > 0; off >>= 1)
                sq += __shfl_xor_sync(0xffffffffu, sq, off);
            const float inv = rsqrtf(sq * (1.f / D) + 1e-5f);

            float4 res;
            float* rp = (float*)&res;
#pragma unroll
            for (int jj = 0; jj < 4; ++jj) {
                const int c = lane * 4 + jj;
                rp[jj] = fmaxf(fmaf((o[jj] - mu) * inv, s_vec[2 * D + c], s_vec[3 * D + c]), 0.f);
            }
            *(float4*)(hout + (size_t)r * D + lane * 4) = res;
        }
    }
}

extern "C" void kernel_launch(void* const* d_in, const int* in_sizes, int n_in,
                              void* d_out, int out_size)
{
    const float* x     = (const float*)d_in[0];
    const float* eattr = (const float*)d_in[1];
    const float* lin_w = (const float*)d_in[2];
    const float* ew1   = (const float*)d_in[3];
    const float* eb1   = (const float*)d_in[4];
    const float* ew2   = (const float*)d_in[5];
    const float* eb2   = (const float*)d_in[6];
    const float* bias  = (const float*)d_in[7];
    const float* lnw   = (const float*)d_in[8];
    const float* lnb   = (const float*)d_in[9];
    const int*   eidx  = (const int*)d_in[10];
    float* out = (float*)d_out;

    cudaFuncSetAttribute(k_node, cudaFuncAttributeMaxDynamicSharedMemorySize, NODE_SMEM);

    const int* erow = eidx;
    const int* ecol = eidx + EE;

    k_zero_deg<<<(NN + 1023) / 1024, 1024>>>();
    k_deg<<<(EE + 255) / 256, 256>>>(ecol);
    k_scan1<<<NSB, 1024>>>();
    k_scan2<<<1, 32>>>();
    k_fin<<<NSB, 1024>>>();
    k_perm<<<(EE + 255) / 256, 256>>>(erow, ecol, eattr);

    for (int l = 0; l < 3; ++l) {
        k_agg<<<AGG_BLOCKS, 256>>>(x, ew1 + l * DE * D, eb1 + l * D, l);
        k_node<<<152, 512, NODE_SMEM>>>(lin_w + l * D * D, ew2 + l * D * D,
                                        eb2 + l * D, bias + l * D,
                                        lnw + l * D, lnb + l * D, out, l);
    }
}

// round 17
// speedup vs baseline: 1.5501x; 1.5501x over previous
#include <cuda_runtime.h>
#include <cstdint>

#define NN 50000
#define EE 800000
#define D  128
#define DE 16
#define NSB 49           // scan blocks: ceil(50000/1024)
#define AGG_BLOCKS 296   // 148 SMs x 2 resident blocks -> 2368 persistent warps

#define NODE_SMEM (2*D*D*4 + 4*D*4)

// Scratch (static __device__ arrays: no allocation allowed)
__device__ float g_h[2][NN * D];
__device__ float g_S[NN * D];
__device__ float g_Z[NN * D];
__device__ int   g_deg[NN];
__device__ float g_gn[NN];
__device__ int   g_off[NN + 1];
__device__ int   g_cur[NN];
__device__ int   g_pre[NN];                 // block-local exclusive prefix
__device__ int   g_bsum[64];                // per-block sums -> exclusive prefix
__device__ int2  g_prw[EE];                 // {row, bitcast(w)} dest-sorted
__device__ float g_eas[(size_t)EE * DE];    // edge_attr in dest-sorted order

#define PACK2(d, x)      asm("mov.b64 %0, {%1, %1};" : "=l"(d) : "f"(x))
#define FMA2(d, a, b, c) asm("fma.rn.f32x2 %0, %1, %2, %3;" : "=l"(d) : "l"(a), "l"(b), "l"(c))

__global__ void k_zero_deg() {
    int i = blockIdx.x * blockDim.x + threadIdx.x;
    if (i < NN) g_deg[i] = 0;
}

__global__ void k_deg(const int* __restrict__ col) {
    int e = blockIdx.x * blockDim.x + threadIdx.x;
    if (e < EE) atomicAdd(&g_deg[col[e]], 1);
}

// Pass 1: block-local exclusive scan of g_deg; write local prefix + block sum.
__global__ __launch_bounds__(1024) void k_scan1() {
    __shared__ int sw[32];
    const int t = threadIdx.x, lane = t & 31, wid = t >> 5;
    const int i = blockIdx.x * 1024 + t;
    const int v = (i < NN) ? g_deg[i] : 0;
    int x = v;
#pragma unroll
    for (int o = 1; o < 32; o <<= 1) {
        int y = __shfl_up_sync(0xffffffffu, x, o);
        if (lane >= o) x += y;
    }
    if (lane == 31) sw[wid] = x;
    __syncthreads();
    if (wid == 0) {
        int s = sw[lane];
#pragma unroll
        for (int o = 1; o < 32; o <<= 1) {
            int y = __shfl_up_sync(0xffffffffu, s, o);
            if (lane >= o) s += y;
        }
        sw[lane] = s;
    }
    __syncthreads();
    const int pre = (wid ? sw[wid - 1] : 0) + x - v;  // exclusive within block
    if (i < NN) g_pre[i] = pre;
    if (t == 1023) g_bsum[blockIdx.x] = pre + v;
}

// Pass 2: one warp scans the 49 block sums (exclusive).
__global__ void k_scan2() {
    const int lane = threadIdx.x;
    if (lane >= 32) return;
    int a = 0, b = 0;
    if (lane < NSB) a = g_bsum[lane];
    if (lane + 32 < NSB) b = g_bsum[lane + 32];
    const int a0 = a, b0 = b;
#pragma unroll
    for (int o = 1; o < 32; o <<= 1) {
        int y = __shfl_up_sync(0xffffffffu, a, o);
        if (lane >= o) a += y;
    }
    const int totA = __shfl_sync(0xffffffffu, a, 31);
#pragma unroll
    for (int o = 1; o < 32; o <<= 1) {
        int y = __shfl_up_sync(0xffffffffu, b, o);
        if (lane >= o) b += y;
    }
    if (lane < NSB) g_bsum[lane] = a - a0;
    if (lane + 32 < NSB) g_bsum[lane + 32] = totA + b - b0;
}

// Pass 3: finalize offsets, cursors, gcn-norm factors.
__global__ __launch_bounds__(1024) void k_fin() {
    const int i = blockIdx.x * 1024 + threadIdx.x;
    if (i < NN) {
        const int o = g_pre[i] + g_bsum[blockIdx.x];
        g_off[i] = o;
        g_cur[i] = o;
        const int d = g_deg[i];
        g_gn[i] = (d > 0) ? rsqrtf((float)d) : 0.f;
    }
    if (i == 0) g_off[NN] = EE;
}

// Counting-sort permute: edge e -> slot pos (sorted by destination col).
__global__ void k_perm(const int* __restrict__ row, const int* __restrict__ col,
                       const float* __restrict__ eattr) {
    int e = blockIdx.x * blockDim.x + threadIdx.x;
    if (e >= EE) return;
    const int c = col[e];
    const int r = row[e];
    const int pos = atomicAdd(&g_cur[c], 1);
    g_prw[pos] = make_int2(r, __float_as_int(g_gn[r] * g_gn[c]));
    const float4* src = (const float4*)(eattr + (size_t)e * DE);
    float4* dst = (float4*)(g_eas + (size_t)pos * DE);
    dst[0] = src[0]; dst[1] = src[1]; dst[2] = src[2]; dst[3] = src[3];
}

// Persistent warps: W1/b1 loaded ONCE per warp, then a grid-stride loop over
// destination nodes running round-7's exact 2-edge-unrolled body.
__global__ __launch_bounds__(256, 2) void k_agg(
    const float* __restrict__ x,
    const float* __restrict__ w1,
    const float* __restrict__ b1,
    int layer)
{
    const float* __restrict__ h = (layer == 0) ? x : g_h[(layer - 1) & 1];
    const int lane = threadIdx.x & 31;

    // W1 columns for this lane in registers as f32x2 pairs (amortized over ~21 nodes)
    unsigned long long w101[DE], w123[DE], b101, b123;
    {
        const ulonglong2 bv = *(const ulonglong2*)(b1 + lane * 4);
        b101 = bv.x; b123 = bv.y;
#pragma unroll
        for (int k = 0; k < DE; ++k) {
            const ulonglong2 wv = *(const ulonglong2*)(w1 + k * D + lane * 4);
            w101[k] = wv.x; w123[k] = wv.y;
        }
    }

    const int warp   = blockIdx.x * 8 + (threadIdx.x >> 5);
    const int nwarps = gridDim.x * 8;

    for (int node = warp; node < NN; node += nwarps) {
        const int j0 = g_off[node], j1 = g_off[node + 1];
        const int cnt = j1 - j0;

        unsigned long long s01 = 0ull, s23 = 0ull;
        float az0 = 0.f, az1 = 0.f, az2 = 0.f, az3 = 0.f;

        const int npairs = cnt >> 1;
        const bool tail = (cnt & 1) != 0;

        int2 rwA = make_int2(0, 0), rwB = make_int2(0, 0);
        float aA = 0.f, aB = 0.f;
        if (cnt > 0) {
            rwA = __ldg(g_prw + j0);
            aA = (lane < DE) ? __ldg(g_eas + (size_t)j0 * DE + lane) : 0.f;
        }
        if (npairs > 0) {
            rwB = __ldg(g_prw + j0 + 1);
            aB = (lane < DE) ? __ldg(g_eas + (size_t)(j0 + 1) * DE + lane) : 0.f;
        }

        int j = j0;
        for (int p = 0; p < npairs; ++p) {
            const ulonglong2 hvA = __ldg((const ulonglong2*)(h + (size_t)rwA.x * D + lane * 4));
            const ulonglong2 hvB = __ldg((const ulonglong2*)(h + (size_t)rwB.x * D + lane * 4));
            const float wA = __int_as_float(rwA.y);
            const float wB = __int_as_float(rwB.y);
            const float aAc = aA, aBc = aB;

            const int jn = j + 2;
            if (p + 1 < npairs) {
                rwA = __ldg(g_prw + jn);
                rwB = __ldg(g_prw + jn + 1);
                aA = (lane < DE) ? __ldg(g_eas + (size_t)jn * DE + lane) : 0.f;
                aB = (lane < DE) ? __ldg(g_eas + (size_t)(jn + 1) * DE + lane) : 0.f;
            } else if (tail) {
                rwA = __ldg(g_prw + jn);
                aA = (lane < DE) ? __ldg(g_eas + (size_t)jn * DE + lane) : 0.f;
            }

            // two independent edge-MLP chains
            unsigned long long zA01 = b101, zA23 = b123, zB01 = b101, zB23 = b123;
#pragma unroll
            for (int k = 0; k < DE; ++k) {
                const float akA = __shfl_sync(0xffffffffu, aAc, k);
                const float akB = __shfl_sync(0xffffffffu, aBc, k);
                unsigned long long tA, tB;
                PACK2(tA, akA);
                PACK2(tB, akB);
                FMA2(zA01, tA, w101[k], zA01);
                FMA2(zB01, tB, w101[k], zB01);
                FMA2(zA23, tA, w123[k], zA23);
                FMA2(zB23, tB, w123[k], zB23);
            }
            {
                const float2 p01 = *(const float2*)&zA01, p23 = *(const float2*)&zA23;
                const float2 q01 = *(const float2*)&zB01, q23 = *(const float2*)&zB23;
                az0 += fmaxf(p01.x, 0.f) + fmaxf(q01.x, 0.f);
                az1 += fmaxf(p01.y, 0.f) + fmaxf(q01.y, 0.f);
                az2 += fmaxf(p23.x, 0.f) + fmaxf(q23.x, 0.f);
                az3 += fmaxf(p23.y, 0.f) + fmaxf(q23.y, 0.f);
            }
            unsigned long long wp;
            PACK2(wp, wA);
            FMA2(s01, wp, hvA.x, s01);
            FMA2(s23, wp, hvA.y, s23);
            PACK2(wp, wB);
            FMA2(s01, wp, hvB.x, s01);
            FMA2(s23, wp, hvB.y, s23);
            j = jn;
        }

        if (tail) {
            // metadata already in rwA/aA (prefetched by last pair, or the cnt>0 init)
            const ulonglong2 hvA = __ldg((const ulonglong2*)(h + (size_t)rwA.x * D + lane * 4));
            const float wA = __int_as_float(rwA.y);
            unsigned long long zA01 = b101, zA23 = b123;
#pragma unroll
            for (int k = 0; k < DE; ++k) {
                const float ak = __shfl_sync(0xffffffffu, aA, k);
                unsigned long long tA; PACK2(tA, ak);
                FMA2(zA01, tA, w101[k], zA01);
                FMA2(zA23, tA, w123[k], zA23);
            }
            const float2 p01 = *(const float2*)&zA01, p23 = *(const float2*)&zA23;
            az0 += fmaxf(p01.x, 0.f);
            az1 += fmaxf(p01.y, 0.f);
            az2 += fmaxf(p23.x, 0.f);
            az3 += fmaxf(p23.y, 0.f);
            unsigned long long wp; PACK2(wp, wA);
            FMA2(s01, wp, hvA.x, s01);
            FMA2(s23, wp, hvA.y, s23);
        }

        ulonglong2 so; so.x = s01; so.y = s23;
        *(ulonglong2*)(g_S + (size_t)node * D + lane * 4) = so;
        *(float4*)(g_Z + (size_t)node * D + lane * 4) = make_float4(az0, az1, az2, az3);
    }
}

// Fused: out = S @ lin_w + Z @ W2 + deg*b2 + bias ; LayerNorm ; relu  (f32x2 GEMM)
// Grid is 148 (= SM count): 1 block/SM (130KB smem), SINGLE wave — the old 152
// grid ran a 2nd wave of 4 straggler blocks serially, ~doubling the critical path.
__global__ __launch_bounds__(512, 1) void k_node(
    const float* __restrict__ lw,
    const float* __restrict__ w2,
    const float* __restrict__ b2,
    const float* __restrict__ bias,
    const float* __restrict__ lnw,
    const float* __restrict__ lnb,
    float* __restrict__ dout,
    int layer)
{
    extern __shared__ __align__(16) float sm[];
    float* s_lw  = sm;
    float* s_w2  = sm + D * D;
    float* s_vec = sm + 2 * D * D;   // [b2 | bias | lnw | lnb]

    for (int i = threadIdx.x; i < D * D / 4; i += 512) {
        ((float4*)s_lw)[i] = ((const float4*)lw)[i];
        ((float4*)s_w2)[i] = ((const float4*)w2)[i];
    }
    if (threadIdx.x < D) {
        s_vec[threadIdx.x]         = b2[threadIdx.x];
        s_vec[D     + threadIdx.x] = bias[threadIdx.x];
        s_vec[2 * D + threadIdx.x] = lnw[threadIdx.x];
        s_vec[3 * D + threadIdx.x] = lnb[threadIdx.x];
    }
    __syncthreads();

    float* hout = (layer == 2) ? dout : g_h[layer & 1];
    const int lane = threadIdx.x & 31;
    const int wid  = threadIdx.x >> 5;
    const ulonglong2* lw2 = (const ulonglong2*)s_lw;
    const ulonglong2* w22 = (const ulonglong2*)s_w2;

    for (int tile = blockIdx.x * 64; tile < NN; tile += gridDim.x * 64) {
        const int r0 = tile + wid * 4;
        unsigned long long acc01[4], acc23[4];
#pragma unroll
        for (int i = 0; i < 4; ++i) { acc01[i] = 0ull; acc23[i] = 0ull; }

#pragma unroll 2
        for (int k = 0; k < D; k += 4) {
            float4 sv[4], zv[4];
#pragma unroll
            for (int i = 0; i < 4; ++i) {
                const int r = r0 + i;
                if (r < NN) {
                    sv[i] = __ldg((const float4*)(g_S + (size_t)r * D + k));
                    zv[i] = __ldg((const float4*)(g_Z + (size_t)r * D + k));
                } else {
                    sv[i] = make_float4(0.f, 0.f, 0.f, 0.f);
                    zv[i] = make_float4(0.f, 0.f, 0.f, 0.f);
                }
            }
#pragma unroll
            for (int kk = 0; kk < 4; ++kk) {
                const ulonglong2 wl = lw2[(k + kk) * 32 + lane];
                const ulonglong2 wv = w22[(k + kk) * 32 + lane];
#pragma unroll
                for (int i = 0; i < 4; ++i) {
                    const float sx = ((const float*)&sv[i])[kk];
                    const float zx = ((const float*)&zv[i])[kk];
                    unsigned long long sx2, zx2;
                    PACK2(sx2, sx);
                    PACK2(zx2, zx);
                    FMA2(acc01[i], sx2, wl.x, acc01[i]);
                    FMA2(acc01[i], zx2, wv.x, acc01[i]);
                    FMA2(acc23[i], sx2, wl.y, acc23[i]);
                    FMA2(acc23[i], zx2, wv.y, acc23[i]);
                }
            }
        }

        // Epilogue: +deg*b2 +bias, LayerNorm, relu, store
#pragma unroll
        for (int i = 0; i < 4; ++i) {
            const int r = r0 + i;
            if (r >= NN) continue;
            const float dg = (float)g_deg[r];
            const float2 a01 = *(const float2*)&acc01[i];
            const float2 a23 = *(const float2*)&acc23[i];
            float o[4] = { a01.x, a01.y, a23.x, a23.y };
#pragma unroll
            for (int jj = 0; jj < 4; ++jj) {
                const int c = lane * 4 + jj;
                o[jj] = o[jj] + dg * s_vec[c] + s_vec[D + c];
            }
            float sum = o[0] + o[1] + o[2] + o[3];
#pragma unroll
            for (int off = 16; off > 0; off >>= 1)
                sum += __shfl_xor_sync(0xffffffffu, sum, off);
            const float mu = sum * (1.f / D);
            float sq = 0.f;
#pragma unroll
            for (int jj = 0; jj < 4; ++jj) { const float dd = o[jj] - mu; sq = fmaf(dd, dd, sq); }
#pragma unroll
            for (int off = 16; off > 0; off >>= 1)
                sq += __shfl_xor_sync(0xffffffffu, sq, off);
            const float inv = rsqrtf(sq * (1.f / D) + 1e-5f);

            float4 res;
            float* rp = (float*)&res;
#pragma unroll
            for (int jj = 0; jj < 4; ++jj) {
                const int c = lane * 4 + jj;
                rp[jj] = fmaxf(fmaf((o[jj] - mu) * inv, s_vec[2 * D + c], s_vec[3 * D + c]), 0.f);
            }
            *(float4*)(hout + (size_t)r * D + lane * 4) = res;
        }
    }
}

extern "C" void kernel_launch(void* const* d_in, const int* in_sizes, int n_in,
                              void* d_out, int out_size)
{
    const float* x     = (const float*)d_in[0];
    const float* eattr = (const float*)d_in[1];
    const float* lin_w = (const float*)d_in[2];
    const float* ew1   = (const float*)d_in[3];
    const float* eb1   = (const float*)d_in[4];
    const float* ew2   = (const float*)d_in[5];
    const float* eb2   = (const float*)d_in[6];
    const float* bias  = (const float*)d_in[7];
    const float* lnw   = (const float*)d_in[8];
    const float* lnb   = (const float*)d_in[9];
    const int*   eidx  = (const int*)d_in[10];
    float* out = (float*)d_out;

    cudaFuncSetAttribute(k_node, cudaFuncAttributeMaxDynamicSharedMemorySize, NODE_SMEM);

    const int* erow = eidx;
    const int* ecol = eidx + EE;

    k_zero_deg<<<(NN + 1023) / 1024, 1024>>>();
    k_deg<<<(EE + 255) / 256, 256>>>(ecol);
    k_scan1<<<NSB, 1024>>>();
    k_scan2<<<1, 32>>>();
    k_fin<<<NSB, 1024>>>();
    k_perm<<<(EE + 255) / 256, 256>>>(erow, ecol, eattr);

    for (int l = 0; l < 3; ++l) {
        k_agg<<<AGG_BLOCKS, 256>>>(x, ew1 + l * DE * D, eb1 + l * D, l);
        k_node<<<148, 512, NODE_SMEM>>>(lin_w + l * D * D, ew2 + l * D * D,
                                        eb2 + l * D, bias + l * D,
                                        lnw + l * D, lnb + l * D, out, l);
    }
}